// round 1
// baseline (speedup 1.0000x reference)
#include <cuda_runtime.h>
#include <math.h>

#define NB   8
#define CINX 256
#define NCO  128
#define HH   64
#define WWD  64
#define HWX  4096
#define NK   9
#define EPSV 1e-5f

// ---------------- scratch (device globals; no allocation allowed) ----------------
static __device__ float g_om[NB * 27 * HWX];          // offset conv output   3.5 MB
static __device__ float g_out1[NB * NCO * HWX];        // DCN output (raw)    16.8 MB
static __device__ float g_wT[CINX * NK * NCO];         // w_dcn  -> [c][k][o]  1.2 MB
static __device__ float g_wOffT[CINX * 27 * NK];       // w_off  -> [c][o][j]  0.25 MB
static __device__ float g_wctT[NCO * 16 * NCO];        // w_ct flip -> [c][dh][dw][o] 1 MB
static __device__ float g_stats1[2 * NCO];             // scale / shift (BN1)
static __device__ float g_stats2[2 * NCO];             // scale / shift (BN2)

// ---------------- K0: weight transposes (run every launch; cheap) ----------------
__global__ void k0_transpose(const float* __restrict__ w_dcn,
                             const float* __restrict__ w_off,
                             const float* __restrict__ w_ct) {
    const int n1 = CINX * NK * NCO;   // 294912
    const int n2 = CINX * 27 * NK;    // 62208
    const int n3 = NCO * 16 * NCO;    // 262144
    const int ntot = n1 + n2 + n3;
    for (int idx = blockIdx.x * blockDim.x + threadIdx.x; idx < ntot;
         idx += gridDim.x * blockDim.x) {
        if (idx < n1) {
            const int o = idx & 127;
            const int ck = idx >> 7;
            const int k = ck % 9, c = ck / 9;
            g_wT[idx] = w_dcn[(o * CINX + c) * 9 + k];
        } else if (idx < n1 + n2) {
            const int j2 = idx - n1;
            const int c = j2 / 243;
            const int r = j2 - c * 243;
            const int o = r / 9, j = r - o * 9;
            g_wOffT[j2] = w_off[(o * CINX + c) * 9 + j];
        } else {
            const int j3 = idx - n1 - n2;
            const int o = j3 & 127;
            const int t16 = (j3 >> 7) & 15;
            const int c = j3 >> 11;
            const int dh = t16 >> 2, dw = t16 & 3;
            // pre-apply the flip: wt[o][c][dh][dw] = w_ct[c][o][3-dh][3-dw]
            g_wctT[j3] = w_ct[(c * NCO + o) * 16 + (3 - dh) * 4 + (3 - dw)];
        }
    }
}

// ---------------- K1: offset conv  om[b][27][h][w] ----------------
// block = (b, h); 256 threads: p = t&63 pixel, g = t>>6 output-channel group
__global__ __launch_bounds__(256, 2) void k1_offconv(const float* __restrict__ x,
                                                     const float* __restrict__ b_off) {
    const int b = blockIdx.x >> 6;
    const int h = blockIdx.x & 63;
    const int t = threadIdx.x;
    const int p = t & 63;
    const int g = t >> 6;

    __shared__ float sRow[3][68];
    __shared__ float sW[243];

    float acc[7];
#pragma unroll
    for (int i = 0; i < 7; i++) acc[i] = 0.f;

    const float* xb = x + (size_t)b * CINX * HWX;

    const int rr = t / 66;
    const int xx = t - rr * 66;
    const int gy = h - 1 + rr;
    const int gx = xx - 1;
    const bool xok = (t < 198) && (gy >= 0) && (gy < HH) && (gx >= 0) && (gx < WWD);
    const int xoff = gy * WWD + gx;

    float pre_x = xok ? xb[xoff] : 0.f;
    float pre_w = (t < 243) ? g_wOffT[t] : 0.f;

    for (int c = 0; c < CINX; ++c) {
        __syncthreads();
        if (t < 198) sRow[rr][xx] = pre_x;
        if (t < 243) sW[t] = pre_w;
        __syncthreads();
        if (c + 1 < CINX) {
            pre_x = xok ? xb[(size_t)(c + 1) * HWX + xoff] : 0.f;
            pre_w = (t < 243) ? g_wOffT[(c + 1) * 243 + t] : 0.f;
        }
        float xv[9];
#pragma unroll
        for (int r = 0; r < 3; r++)
#pragma unroll
            for (int cc = 0; cc < 3; cc++) xv[r * 3 + cc] = sRow[r][p + cc];
#pragma unroll
        for (int i = 0; i < 7; i++) {
            const int o = g + 4 * i;
            if (o < 27) {
#pragma unroll
                for (int j = 0; j < 9; j++) acc[i] = fmaf(sW[o * 9 + j], xv[j], acc[i]);
            }
        }
    }
#pragma unroll
    for (int i = 0; i < 7; i++) {
        const int o = g + 4 * i;
        if (o < 27) g_om[(((size_t)b * 27 + o) * 64 + h) * 64 + p] = acc[i] + b_off[o];
    }
}

// ---------------- K2: deformable sampling + GEMM -> out1 ----------------
// block = (b, h). Per block: out1[b, 0:128, h, 0:64] = sum_{c,k} wT * sampled
#define GATHER(xc, item)                                            \
    (sWgt[0][(item)] * (xc)[sIdx[0][(item)]] +                      \
     sWgt[1][(item)] * (xc)[sIdx[1][(item)]] +                      \
     sWgt[2][(item)] * (xc)[sIdx[2][(item)]] +                      \
     sWgt[3][(item)] * (xc)[sIdx[3][(item)]])

__global__ __launch_bounds__(256, 2) void k2_dcn(const float* __restrict__ x,
                                                 const float* __restrict__ b_dcn) {
    const int b = blockIdx.x >> 6;
    const int h = blockIdx.x & 63;
    const int t = threadIdx.x;

    __shared__ int sIdx[4][576];
    __shared__ float sWgt[4][576];
    __shared__ float sSamp[576];   // [k*64 + p]
    __shared__ float sWc[1152];    // [k*128 + o]

    // Phase A: bilinear params (mask folded into weights)
    for (int item = t; item < 576; item += 256) {
        const int k = item >> 6, p = item & 63;
        const float oy = g_om[((b * 27 + k) * 64 + h) * 64 + p];
        const float ox = g_om[((b * 27 + 9 + k) * 64 + h) * 64 + p];
        const float mm = g_om[((b * 27 + 18 + k) * 64 + h) * 64 + p];
        const float mask = 1.0f / (1.0f + expf(-mm));
        const float py = oy + (float)(h - 1 + k / 3);
        const float px = ox + (float)(p - 1 + k % 3);
        const float y0f = floorf(py), x0f = floorf(px);
        const int y0 = (int)y0f, x0 = (int)x0f;
        const float ly = py - y0f, lx = px - x0f;
        const float wy0 = 1.0f - ly, wx0 = 1.0f - lx;
#pragma unroll
        for (int q = 0; q < 4; q++) {
            const int yi = y0 + (q >> 1), xi = x0 + (q & 1);
            const bool valid = (yi >= 0) && (yi < HH) && (xi >= 0) && (xi < WWD);
            const int yc = min(max(yi, 0), HH - 1);
            const int xc = min(max(xi, 0), WWD - 1);
            sIdx[q][item] = yc * WWD + xc;
            const float wq = ((q >> 1) ? ly : wy0) * ((q & 1) ? lx : wx0);
            sWgt[q][item] = valid ? wq * mask : 0.0f;
        }
    }
    __syncthreads();

    const float* xb = x + (size_t)b * CINX * HWX;
    const int obase = (t & 15) * 8;
    const int pbase = (t >> 4) * 4;
    float acc[8][4];
#pragma unroll
    for (int i = 0; i < 8; i++)
#pragma unroll
        for (int j = 0; j < 4; j++) acc[i][j] = 0.0f;

    const bool it2ok = (t < 64);
    float s0, s1, s2 = 0.f;
    float4 wr0, wr1 = make_float4(0.f, 0.f, 0.f, 0.f);

    // prefetch c = 0
    {
        const float* xc = xb;
        s0 = GATHER(xc, t);
        s1 = GATHER(xc, t + 256);
        if (it2ok) s2 = GATHER(xc, t + 512);
        const float4* wp = (const float4*)g_wT;
        wr0 = wp[t];
        if (t < 32) wr1 = wp[256 + t];
    }

    for (int c = 0; c < CINX; ++c) {
        __syncthreads();
        sSamp[t] = s0;
        sSamp[t + 256] = s1;
        if (it2ok) sSamp[t + 512] = s2;
        ((float4*)sWc)[t] = wr0;
        if (t < 32) ((float4*)sWc)[256 + t] = wr1;
        __syncthreads();
        if (c + 1 < CINX) {
            const float* xc = xb + (size_t)(c + 1) * HWX;
            s0 = GATHER(xc, t);
            s1 = GATHER(xc, t + 256);
            if (it2ok) s2 = GATHER(xc, t + 512);
            const float4* wp = (const float4*)(g_wT + (c + 1) * 1152);
            wr0 = wp[t];
            if (t < 32) wr1 = wp[256 + t];
        }
#pragma unroll
        for (int k = 0; k < NK; ++k) {
            const float4 w0 = *(const float4*)(sWc + k * 128 + obase);
            const float4 w1 = *(const float4*)(sWc + k * 128 + obase + 4);
            const float4 sv = *(const float4*)(sSamp + k * 64 + pbase);
            const float wv[8] = {w0.x, w0.y, w0.z, w0.w, w1.x, w1.y, w1.z, w1.w};
            const float pv[4] = {sv.x, sv.y, sv.z, sv.w};
#pragma unroll
            for (int i = 0; i < 8; i++)
#pragma unroll
                for (int j = 0; j < 4; j++) acc[i][j] = fmaf(wv[i], pv[j], acc[i][j]);
        }
    }
#pragma unroll
    for (int i = 0; i < 8; i++) {
        const int o = obase + i;
        const float bias = b_dcn[o];
#pragma unroll
        for (int j = 0; j < 4; j++)
            g_out1[(((size_t)b * NCO + o) * 64 + h) * 64 + pbase + j] = acc[i][j] + bias;
    }
}

// ---------------- K3: BN1 stats -> scale/shift ----------------
__global__ void k3_stats1(const float* __restrict__ gamma, const float* __restrict__ beta) {
    const int ch = blockIdx.x;
    const int t = threadIdx.x;
    float s = 0.f, q = 0.f;
    for (int b = 0; b < NB; b++) {
        const float4* pch = (const float4*)(g_out1 + ((size_t)b * NCO + ch) * HWX);
        for (int i = t; i < HWX / 4; i += 256) {
            const float4 v = pch[i];
            s += v.x + v.y + v.z + v.w;
            q += v.x * v.x + v.y * v.y + v.z * v.z + v.w * v.w;
        }
    }
    __shared__ float rs[256], rq[256];
    rs[t] = s; rq[t] = q;
    __syncthreads();
    for (int off = 128; off > 0; off >>= 1) {
        if (t < off) { rs[t] += rs[t + off]; rq[t] += rq[t + off]; }
        __syncthreads();
    }
    if (t == 0) {
        const float n = (float)(NB * HWX);
        const float mean = rs[0] / n;
        const float var = rq[0] / n - mean * mean;
        const float sc = rsqrtf(var + EPSV) * gamma[ch];
        g_stats1[ch] = sc;
        g_stats1[NCO + ch] = beta[ch] - mean * sc;
    }
}

// ---------------- K4: transposed conv (BN1+ReLU fused on input) -> out2 raw ----------------
// block = (b, Y, X-half of 64). out2[b, 0:128, Y, X0:X0+64]
__global__ __launch_bounds__(256, 2) void k4_tconv(float* __restrict__ out2) {
    const int blk = blockIdx.x;
    const int b = blk >> 8;
    const int Y = (blk >> 1) & 127;
    const int X0 = (blk & 1) * 64;
    const int t = threadIdx.x;
    const int Ypar = Y & 1;
    const int y0r = (Y - 2 + Ypar) / 2;  // exact even division
    const int y1r = y0r + 1;

    __shared__ float sIn[2][68];
    __shared__ float sW[1024];  // [j*128 + o], j = r*4 + dw

    const int obase = (t & 15) * 8;
    const int Xl = (t >> 4) * 4;

    float acc[4][8];
#pragma unroll
    for (int xo = 0; xo < 4; xo++)
#pragma unroll
        for (int i = 0; i < 8; i++) acc[xo][i] = 0.f;

    // input-row staging role (t < 132)
    const int rr = (t < 132) ? (t / 66) : 0;
    const int xx = (t < 132) ? (t - rr * 66) : 0;
    const int yrow = rr ? y1r : y0r;
    const int gx = xx - 1;
    const bool instage =
        (t < 132) && (yrow >= 0) && (yrow < HH) && (gx >= 0) && (gx < WWD);
    const int inoff0 = yrow * WWD + gx;

    // weight staging role: j = t>>5, o-lane = (t&31)*4
    const int wj = t >> 5;
    const int wdh = Ypar + 2 * (wj >> 2);
    const int wdw = wj & 3;

    float vin, sc_c, sh_c;
    float4 wv4;
    // prefetch c = 0
    vin = instage ? g_out1[((size_t)b * NCO) * HWX + inoff0] : 0.f;
    sc_c = g_stats1[0];
    sh_c = g_stats1[NCO];
    wv4 = ((const float4*)(g_wctT + (wdh * 4 + wdw) * 128))[t & 31];

    for (int c = 0; c < NCO; ++c) {
        __syncthreads();
        if (t < 132)
            sIn[rr][xx] = instage ? fmaxf(0.f, fmaf(vin, sc_c, sh_c)) : 0.f;
        ((float4*)sW)[t] = wv4;
        __syncthreads();
        if (c + 1 < NCO) {
            vin = instage ? g_out1[((size_t)b * NCO + (c + 1)) * HWX + inoff0] : 0.f;
            sc_c = g_stats1[c + 1];
            sh_c = g_stats1[NCO + c + 1];
            wv4 = ((const float4*)(g_wctT + (((c + 1) * 16 + wdh * 4 + wdw) * 128)))[t & 31];
        }
#pragma unroll
        for (int j = 0; j < 8; ++j) {
            const int r = j >> 2;
            const int dw = j & 3;
            const float4 w0 = *(const float4*)(sW + j * 128 + obase);
            const float4 w1 = *(const float4*)(sW + j * 128 + obase + 4);
            const float wv[8] = {w0.x, w0.y, w0.z, w0.w, w1.x, w1.y, w1.z, w1.w};
#pragma unroll
            for (int u = 0; u < 2; ++u) {
                const int xo = (dw & 1) + 2 * u;
                const int X = X0 + Xl + xo;
                const int col = ((X + (X & 1)) >> 1) + (dw >> 1);
                const float v = sIn[r][col];
#pragma unroll
                for (int i = 0; i < 8; i++) acc[xo][i] = fmaf(wv[i], v, acc[xo][i]);
            }
        }
    }
#pragma unroll
    for (int xo = 0; xo < 4; xo++) {
        const int X = X0 + Xl + xo;
#pragma unroll
        for (int i = 0; i < 8; i++)
            out2[(((size_t)b * NCO + obase + i) * 128 + Y) * 128 + X] = acc[xo][i];
    }
}

// ---------------- K5: BN2 stats over raw out2 ----------------
__global__ void k5_stats2(const float* __restrict__ out2,
                          const float* __restrict__ gamma,
                          const float* __restrict__ beta) {
    const int ch = blockIdx.x;
    const int t = threadIdx.x;
    float s = 0.f, q = 0.f;
    for (int b = 0; b < NB; b++) {
        const float4* pch = (const float4*)(out2 + ((size_t)b * NCO + ch) * 16384);
        for (int i = t; i < 16384 / 4; i += 256) {
            const float4 v = pch[i];
            s += v.x + v.y + v.z + v.w;
            q += v.x * v.x + v.y * v.y + v.z * v.z + v.w * v.w;
        }
    }
    __shared__ float rs[256], rq[256];
    rs[t] = s; rq[t] = q;
    __syncthreads();
    for (int off = 128; off > 0; off >>= 1) {
        if (t < off) { rs[t] += rs[t + off]; rq[t] += rq[t + off]; }
        __syncthreads();
    }
    if (t == 0) {
        const float n = (float)(NB * 16384);
        const float mean = rs[0] / n;
        const float var = rq[0] / n - mean * mean;
        const float sc = rsqrtf(var + EPSV) * gamma[ch];
        g_stats2[ch] = sc;
        g_stats2[NCO + ch] = beta[ch] - mean * sc;
    }
}

// ---------------- K6: in-place BN2 + ReLU on d_out ----------------
__global__ void k6_bnrelu(float* __restrict__ out) {
    const int n4 = NB * NCO * 128 * 128 / 4;
    int i4 = blockIdx.x * blockDim.x + threadIdx.x;
    if (i4 < n4) {
        float4 v = ((float4*)out)[i4];
        const int ch = (i4 >> 12) & 127;
        const float sc = g_stats2[ch];
        const float sh = g_stats2[NCO + ch];
        v.x = fmaxf(0.f, fmaf(v.x, sc, sh));
        v.y = fmaxf(0.f, fmaf(v.y, sc, sh));
        v.z = fmaxf(0.f, fmaf(v.z, sc, sh));
        v.w = fmaxf(0.f, fmaf(v.w, sc, sh));
        ((float4*)out)[i4] = v;
    }
}

// ---------------- launch ----------------
extern "C" void kernel_launch(void* const* d_in, const int* in_sizes, int n_in,
                              void* d_out, int out_size) {
    const float* x      = (const float*)d_in[0];
    const float* w_off  = (const float*)d_in[1];
    const float* b_off  = (const float*)d_in[2];
    const float* w_dcn  = (const float*)d_in[3];
    const float* b_dcn  = (const float*)d_in[4];
    const float* gamma1 = (const float*)d_in[5];
    const float* beta1  = (const float*)d_in[6];
    const float* w_ct   = (const float*)d_in[7];
    const float* gamma2 = (const float*)d_in[8];
    const float* beta2  = (const float*)d_in[9];
    float* out = (float*)d_out;

    (void)in_sizes; (void)n_in; (void)out_size;

    k0_transpose<<<256, 256>>>(w_dcn, w_off, w_ct);
    k1_offconv<<<NB * HH, 256>>>(x, b_off);
    k2_dcn<<<NB * HH, 256>>>(x, b_dcn);
    k3_stats1<<<NCO, 256>>>(gamma1, beta1);
    k4_tconv<<<NB * 128 * 2, 256>>>(out);
    k5_stats2<<<NCO, 256>>>(out, gamma2, beta2);
    k6_bnrelu<<<(NB * NCO * 128 * 128 / 4 + 255) / 256, 256>>>(out);
}

// round 2
// speedup vs baseline: 1.0002x; 1.0002x over previous
#include <cuda_runtime.h>
#include <math.h>

#define NB   8
#define CINX 256
#define NCO  128
#define HH   64
#define WWD  64
#define HWX  4096
#define NK   9
#define EPSV 1e-5f

// ---------------- scratch (device globals; no allocation allowed) ----------------
static __device__ float g_om[NB * 27 * HWX];          // offset conv output   3.5 MB
static __device__ float g_out1[NB * NCO * HWX];        // DCN output (raw)    16.8 MB
static __device__ float g_wT[CINX * NK * NCO];         // w_dcn  -> [c][k][o]  1.2 MB
static __device__ float g_wOffT[CINX * 27 * NK];       // w_off  -> [c][o][j]  0.25 MB
static __device__ float g_wctT[NCO * 16 * NCO];        // w_ct flip -> [c][dh][dw][o] 1 MB
static __device__ float g_stats1[2 * NCO];             // scale / shift (BN1)
static __device__ float g_stats2[2 * NCO];             // scale / shift (BN2)

// ---------------- K0: weight transposes (run every launch; cheap) ----------------
__global__ void k0_transpose(const float* __restrict__ w_dcn,
                             const float* __restrict__ w_off,
                             const float* __restrict__ w_ct) {
    const int n1 = CINX * NK * NCO;   // 294912
    const int n2 = CINX * 27 * NK;    // 62208
    const int n3 = NCO * 16 * NCO;    // 262144
    const int ntot = n1 + n2 + n3;
    for (int idx = blockIdx.x * blockDim.x + threadIdx.x; idx < ntot;
         idx += gridDim.x * blockDim.x) {
        if (idx < n1) {
            const int o = idx & 127;
            const int ck = idx >> 7;
            const int k = ck % 9, c = ck / 9;
            g_wT[idx] = w_dcn[(o * CINX + c) * 9 + k];
        } else if (idx < n1 + n2) {
            const int j2 = idx - n1;
            const int c = j2 / 243;
            const int r = j2 - c * 243;
            const int o = r / 9, j = r - o * 9;
            g_wOffT[j2] = w_off[(o * CINX + c) * 9 + j];
        } else {
            const int j3 = idx - n1 - n2;
            const int o = j3 & 127;
            const int t16 = (j3 >> 7) & 15;
            const int c = j3 >> 11;
            const int dh = t16 >> 2, dw = t16 & 3;
            // pre-apply the flip: wt[o][c][dh][dw] = w_ct[c][o][3-dh][3-dw]
            g_wctT[j3] = w_ct[(c * NCO + o) * 16 + (3 - dh) * 4 + (3 - dw)];
        }
    }
}

// ---------------- K1: offset conv  om[b][27][h][w] ----------------
// block = (b, h); 256 threads: p = t&63 pixel, g = t>>6 output-channel group
__global__ __launch_bounds__(256, 2) void k1_offconv(const float* __restrict__ x,
                                                     const float* __restrict__ b_off) {
    const int b = blockIdx.x >> 6;
    const int h = blockIdx.x & 63;
    const int t = threadIdx.x;
    const int p = t & 63;
    const int g = t >> 6;

    __shared__ float sRow[3][68];
    __shared__ float sW[243];

    float acc[7];
#pragma unroll
    for (int i = 0; i < 7; i++) acc[i] = 0.f;

    const float* xb = x + (size_t)b * CINX * HWX;

    const int rr = t / 66;
    const int xx = t - rr * 66;
    const int gy = h - 1 + rr;
    const int gx = xx - 1;
    const bool xok = (t < 198) && (gy >= 0) && (gy < HH) && (gx >= 0) && (gx < WWD);
    const int xoff = gy * WWD + gx;

    float pre_x = xok ? xb[xoff] : 0.f;
    float pre_w = (t < 243) ? g_wOffT[t] : 0.f;

    for (int c = 0; c < CINX; ++c) {
        __syncthreads();
        if (t < 198) sRow[rr][xx] = pre_x;
        if (t < 243) sW[t] = pre_w;
        __syncthreads();
        if (c + 1 < CINX) {
            pre_x = xok ? xb[(size_t)(c + 1) * HWX + xoff] : 0.f;
            pre_w = (t < 243) ? g_wOffT[(c + 1) * 243 + t] : 0.f;
        }
        float xv[9];
#pragma unroll
        for (int r = 0; r < 3; r++)
#pragma unroll
            for (int cc = 0; cc < 3; cc++) xv[r * 3 + cc] = sRow[r][p + cc];
#pragma unroll
        for (int i = 0; i < 7; i++) {
            const int o = g + 4 * i;
            if (o < 27) {
#pragma unroll
                for (int j = 0; j < 9; j++) acc[i] = fmaf(sW[o * 9 + j], xv[j], acc[i]);
            }
        }
    }
#pragma unroll
    for (int i = 0; i < 7; i++) {
        const int o = g + 4 * i;
        if (o < 27) g_om[(((size_t)b * 27 + o) * 64 + h) * 64 + p] = acc[i] + b_off[o];
    }
}

// ---------------- K2: deformable sampling + GEMM -> out1 ----------------
// block = (b, h). Per block: out1[b, 0:128, h, 0:64] = sum_{c,k} wT * sampled
#define GATHER(xc, item)                                            \
    (sWgt[0][(item)] * (xc)[sIdx[0][(item)]] +                      \
     sWgt[1][(item)] * (xc)[sIdx[1][(item)]] +                      \
     sWgt[2][(item)] * (xc)[sIdx[2][(item)]] +                      \
     sWgt[3][(item)] * (xc)[sIdx[3][(item)]])

__global__ __launch_bounds__(256, 2) void k2_dcn(const float* __restrict__ x,
                                                 const float* __restrict__ b_dcn) {
    const int b = blockIdx.x >> 6;
    const int h = blockIdx.x & 63;
    const int t = threadIdx.x;

    __shared__ int sIdx[4][576];
    __shared__ float sWgt[4][576];
    __shared__ float sSamp[576];   // [k*64 + p]
    __shared__ float sWc[1152];    // [k*128 + o]

    // Phase A: bilinear params (mask folded into weights)
    for (int item = t; item < 576; item += 256) {
        const int k = item >> 6, p = item & 63;
        const float oy = g_om[((b * 27 + k) * 64 + h) * 64 + p];
        const float ox = g_om[((b * 27 + 9 + k) * 64 + h) * 64 + p];
        const float mm = g_om[((b * 27 + 18 + k) * 64 + h) * 64 + p];
        const float mask = 1.0f / (1.0f + expf(-mm));
        const float py = oy + (float)(h - 1 + k / 3);
        const float px = ox + (float)(p - 1 + k % 3);
        const float y0f = floorf(py), x0f = floorf(px);
        const int y0 = (int)y0f, x0 = (int)x0f;
        const float ly = py - y0f, lx = px - x0f;
        const float wy0 = 1.0f - ly, wx0 = 1.0f - lx;
#pragma unroll
        for (int q = 0; q < 4; q++) {
            const int yi = y0 + (q >> 1), xi = x0 + (q & 1);
            const bool valid = (yi >= 0) && (yi < HH) && (xi >= 0) && (xi < WWD);
            const int yc = min(max(yi, 0), HH - 1);
            const int xc = min(max(xi, 0), WWD - 1);
            sIdx[q][item] = yc * WWD + xc;
            const float wq = ((q >> 1) ? ly : wy0) * ((q & 1) ? lx : wx0);
            sWgt[q][item] = valid ? wq * mask : 0.0f;
        }
    }
    __syncthreads();

    const float* xb = x + (size_t)b * CINX * HWX;
    const int obase = (t & 15) * 8;
    const int pbase = (t >> 4) * 4;
    float acc[8][4];
#pragma unroll
    for (int i = 0; i < 8; i++)
#pragma unroll
        for (int j = 0; j < 4; j++) acc[i][j] = 0.0f;

    const bool it2ok = (t < 64);
    float s0, s1, s2 = 0.f;
    float4 wr0, wr1 = make_float4(0.f, 0.f, 0.f, 0.f);

    // prefetch c = 0
    {
        const float* xc = xb;
        s0 = GATHER(xc, t);
        s1 = GATHER(xc, t + 256);
        if (it2ok) s2 = GATHER(xc, t + 512);
        const float4* wp = (const float4*)g_wT;
        wr0 = wp[t];
        if (t < 32) wr1 = wp[256 + t];
    }

    for (int c = 0; c < CINX; ++c) {
        __syncthreads();
        sSamp[t] = s0;
        sSamp[t + 256] = s1;
        if (it2ok) sSamp[t + 512] = s2;
        ((float4*)sWc)[t] = wr0;
        if (t < 32) ((float4*)sWc)[256 + t] = wr1;
        __syncthreads();
        if (c + 1 < CINX) {
            const float* xc = xb + (size_t)(c + 1) * HWX;
            s0 = GATHER(xc, t);
            s1 = GATHER(xc, t + 256);
            if (it2ok) s2 = GATHER(xc, t + 512);
            const float4* wp = (const float4*)(g_wT + (c + 1) * 1152);
            wr0 = wp[t];
            if (t < 32) wr1 = wp[256 + t];
        }
#pragma unroll
        for (int k = 0; k < NK; ++k) {
            const float4 w0 = *(const float4*)(sWc + k * 128 + obase);
            const float4 w1 = *(const float4*)(sWc + k * 128 + obase + 4);
            const float4 sv = *(const float4*)(sSamp + k * 64 + pbase);
            const float wv[8] = {w0.x, w0.y, w0.z, w0.w, w1.x, w1.y, w1.z, w1.w};
            const float pv[4] = {sv.x, sv.y, sv.z, sv.w};
#pragma unroll
            for (int i = 0; i < 8; i++)
#pragma unroll
                for (int j = 0; j < 4; j++) acc[i][j] = fmaf(wv[i], pv[j], acc[i][j]);
        }
    }
#pragma unroll
    for (int i = 0; i < 8; i++) {
        const int o = obase + i;
        const float bias = b_dcn[o];
#pragma unroll
        for (int j = 0; j < 4; j++)
            g_out1[(((size_t)b * NCO + o) * 64 + h) * 64 + pbase + j] = acc[i][j] + bias;
    }
}

// ---------------- K3: BN1 stats -> scale/shift ----------------
__global__ void k3_stats1(const float* __restrict__ gamma, const float* __restrict__ beta) {
    const int ch = blockIdx.x;
    const int t = threadIdx.x;
    float s = 0.f, q = 0.f;
    for (int b = 0; b < NB; b++) {
        const float4* pch = (const float4*)(g_out1 + ((size_t)b * NCO + ch) * HWX);
        for (int i = t; i < HWX / 4; i += 256) {
            const float4 v = pch[i];
            s += v.x + v.y + v.z + v.w;
            q += v.x * v.x + v.y * v.y + v.z * v.z + v.w * v.w;
        }
    }
    __shared__ float rs[256], rq[256];
    rs[t] = s; rq[t] = q;
    __syncthreads();
    for (int off = 128; off > 0; off >>= 1) {
        if (t < off) { rs[t] += rs[t + off]; rq[t] += rq[t + off]; }
        __syncthreads();
    }
    if (t == 0) {
        const float n = (float)(NB * HWX);
        const float mean = rs[0] / n;
        const float var = rq[0] / n - mean * mean;
        const float sc = rsqrtf(var + EPSV) * gamma[ch];
        g_stats1[ch] = sc;
        g_stats1[NCO + ch] = beta[ch] - mean * sc;
    }
}

// ---------------- K4: transposed conv (BN1+ReLU fused on input) -> out2 raw ----------------
// block = (b, Y, X-half of 64). out2[b, 0:128, Y, X0:X0+64]
__global__ __launch_bounds__(256, 2) void k4_tconv(float* __restrict__ out2) {
    const int blk = blockIdx.x;
    const int b = blk >> 8;
    const int Y = (blk >> 1) & 127;
    const int X0 = (blk & 1) * 64;
    const int t = threadIdx.x;
    const int Ypar = Y & 1;
    const int y0r = (Y - 2 + Ypar) / 2;  // exact even division
    const int y1r = y0r + 1;

    __shared__ float sIn[2][68];
    __shared__ float sW[1024];  // [j*128 + o], j = r*4 + dw

    const int obase = (t & 15) * 8;
    const int Xl = (t >> 4) * 4;

    float acc[4][8];
#pragma unroll
    for (int xo = 0; xo < 4; xo++)
#pragma unroll
        for (int i = 0; i < 8; i++) acc[xo][i] = 0.f;

    // input-row staging role (t < 132)
    const int rr = (t < 132) ? (t / 66) : 0;
    const int xx = (t < 132) ? (t - rr * 66) : 0;
    const int yrow = rr ? y1r : y0r;
    const int gx = xx - 1;
    const bool instage =
        (t < 132) && (yrow >= 0) && (yrow < HH) && (gx >= 0) && (gx < WWD);
    const int inoff0 = yrow * WWD + gx;

    // weight staging role: j = t>>5, o-lane = (t&31)*4
    const int wj = t >> 5;
    const int wdh = Ypar + 2 * (wj >> 2);
    const int wdw = wj & 3;

    float vin, sc_c, sh_c;
    float4 wv4;
    // prefetch c = 0
    vin = instage ? g_out1[((size_t)b * NCO) * HWX + inoff0] : 0.f;
    sc_c = g_stats1[0];
    sh_c = g_stats1[NCO];
    wv4 = ((const float4*)(g_wctT + (wdh * 4 + wdw) * 128))[t & 31];

    for (int c = 0; c < NCO; ++c) {
        __syncthreads();
        if (t < 132)
            sIn[rr][xx] = instage ? fmaxf(0.f, fmaf(vin, sc_c, sh_c)) : 0.f;
        ((float4*)sW)[t] = wv4;
        __syncthreads();
        if (c + 1 < NCO) {
            vin = instage ? g_out1[((size_t)b * NCO + (c + 1)) * HWX + inoff0] : 0.f;
            sc_c = g_stats1[c + 1];
            sh_c = g_stats1[NCO + c + 1];
            wv4 = ((const float4*)(g_wctT + (((c + 1) * 16 + wdh * 4 + wdw) * 128)))[t & 31];
        }
#pragma unroll
        for (int j = 0; j < 8; ++j) {
            const int r = j >> 2;
            const int dw = j & 3;
            const float4 w0 = *(const float4*)(sW + j * 128 + obase);
            const float4 w1 = *(const float4*)(sW + j * 128 + obase + 4);
            const float wv[8] = {w0.x, w0.y, w0.z, w0.w, w1.x, w1.y, w1.z, w1.w};
#pragma unroll
            for (int u = 0; u < 2; ++u) {
                const int xo = (dw & 1) + 2 * u;
                const int X = X0 + Xl + xo;
                const int col = ((X + (X & 1)) >> 1) + (dw >> 1);
                const float v = sIn[r][col];
#pragma unroll
                for (int i = 0; i < 8; i++) acc[xo][i] = fmaf(wv[i], v, acc[xo][i]);
            }
        }
    }
#pragma unroll
    for (int xo = 0; xo < 4; xo++) {
        const int X = X0 + Xl + xo;
#pragma unroll
        for (int i = 0; i < 8; i++)
            out2[(((size_t)b * NCO + obase + i) * 128 + Y) * 128 + X] = acc[xo][i];
    }
}

// ---------------- K5: BN2 stats over raw out2 ----------------
__global__ void k5_stats2(const float* __restrict__ out2,
                          const float* __restrict__ gamma,
                          const float* __restrict__ beta) {
    const int ch = blockIdx.x;
    const int t = threadIdx.x;
    float s = 0.f, q = 0.f;
    for (int b = 0; b < NB; b++) {
        const float4* pch = (const float4*)(out2 + ((size_t)b * NCO + ch) * 16384);
        for (int i = t; i < 16384 / 4; i += 256) {
            const float4 v = pch[i];
            s += v.x + v.y + v.z + v.w;
            q += v.x * v.x + v.y * v.y + v.z * v.z + v.w * v.w;
        }
    }
    __shared__ float rs[256], rq[256];
    rs[t] = s; rq[t] = q;
    __syncthreads();
    for (int off = 128; off > 0; off >>= 1) {
        if (t < off) { rs[t] += rs[t + off]; rq[t] += rq[t + off]; }
        __syncthreads();
    }
    if (t == 0) {
        const float n = (float)(NB * 16384);
        const float mean = rs[0] / n;
        const float var = rq[0] / n - mean * mean;
        const float sc = rsqrtf(var + EPSV) * gamma[ch];
        g_stats2[ch] = sc;
        g_stats2[NCO + ch] = beta[ch] - mean * sc;
    }
}

// ---------------- K6: in-place BN2 + ReLU on d_out ----------------
__global__ void k6_bnrelu(float* __restrict__ out) {
    const int n4 = NB * NCO * 128 * 128 / 4;
    int i4 = blockIdx.x * blockDim.x + threadIdx.x;
    if (i4 < n4) {
        float4 v = ((float4*)out)[i4];
        const int ch = (i4 >> 12) & 127;
        const float sc = g_stats2[ch];
        const float sh = g_stats2[NCO + ch];
        v.x = fmaxf(0.f, fmaf(v.x, sc, sh));
        v.y = fmaxf(0.f, fmaf(v.y, sc, sh));
        v.z = fmaxf(0.f, fmaf(v.z, sc, sh));
        v.w = fmaxf(0.f, fmaf(v.w, sc, sh));
        ((float4*)out)[i4] = v;
    }
}

// ---------------- launch ----------------
extern "C" void kernel_launch(void* const* d_in, const int* in_sizes, int n_in,
                              void* d_out, int out_size) {
    const float* x      = (const float*)d_in[0];
    const float* w_off  = (const float*)d_in[1];
    const float* b_off  = (const float*)d_in[2];
    const float* w_dcn  = (const float*)d_in[3];
    const float* b_dcn  = (const float*)d_in[4];
    const float* gamma1 = (const float*)d_in[5];
    const float* beta1  = (const float*)d_in[6];
    const float* w_ct   = (const float*)d_in[7];
    const float* gamma2 = (const float*)d_in[8];
    const float* beta2  = (const float*)d_in[9];
    float* out = (float*)d_out;

    (void)in_sizes; (void)n_in; (void)out_size;

    k0_transpose<<<256, 256>>>(w_dcn, w_off, w_ct);
    k1_offconv<<<NB * HH, 256>>>(x, b_off);
    k2_dcn<<<NB * HH, 256>>>(x, b_dcn);
    k3_stats1<<<NCO, 256>>>(gamma1, beta1);
    k4_tconv<<<NB * 128 * 2, 256>>>(out);
    k5_stats2<<<NCO, 256>>>(out, gamma2, beta2);
    k6_bnrelu<<<(NB * NCO * 128 * 128 / 4 + 255) / 256, 256>>>(out);
}

// round 4
// speedup vs baseline: 2.0836x; 2.0832x over previous
#include <cuda_runtime.h>
#include <cuda_bf16.h>
#include <math.h>
#include <stdint.h>

#define NB 8
#define CINX 256
#define NCO 128
#define HH 64
#define WWD 64
#define HWX 4096
#define EPSV 1e-5f

__device__ __forceinline__ uint32_t smem_u32(const void* p) {
    uint32_t a;
    asm("{ .reg .u64 t; cvta.to.shared.u64 t, %1; cvt.u32.u64 %0, t; }" : "=r"(a) : "l"(p));
    return a;
}
__device__ __forceinline__ void ldsm4(uint32_t addr, uint32_t r[4]) {
    asm volatile("ldmatrix.sync.aligned.m8n8.x4.shared.b16 {%0,%1,%2,%3},[%4];"
                 : "=r"(r[0]), "=r"(r[1]), "=r"(r[2]), "=r"(r[3]) : "r"(addr));
}
__device__ __forceinline__ void mma16816(float d[4], const uint32_t a[4], const uint32_t b0,
                                         const uint32_t b1) {
    asm volatile("mma.sync.aligned.m16n8k16.row.col.f32.bf16.bf16.f32 "
                 "{%0,%1,%2,%3},{%4,%5,%6,%7},{%8,%9},{%0,%1,%2,%3};"
                 : "+f"(d[0]), "+f"(d[1]), "+f"(d[2]), "+f"(d[3])
                 : "r"(a[0]), "r"(a[1]), "r"(a[2]), "r"(a[3]), "r"(b0), "r"(b1));
}
__device__ __forceinline__ uint32_t packsplit(float v0, float v1, uint32_t& lo) {
    __nv_bfloat16 h0 = __float2bfloat16(v0), h1 = __float2bfloat16(v1);
    __nv_bfloat16 l0 = __float2bfloat16(v0 - __bfloat162float(h0));
    __nv_bfloat16 l1 = __float2bfloat16(v1 - __bfloat162float(h1));
    lo = (uint32_t)__bfloat16_as_ushort(l0) | ((uint32_t)__bfloat16_as_ushort(l1) << 16);
    return (uint32_t)__bfloat16_as_ushort(h0) | ((uint32_t)__bfloat16_as_ushort(h1) << 16);
}

// -------- scratch --------
static __device__ float g_om[NB * 27 * HWX];
static __device__ float g_out1[NB * NCO * HWX];
static __device__ float g_wOffT[CINX * 27 * 9];
static __device__ float g_stats1[2 * NCO];
static __device__ float g_stats2[2 * NCO];
// padded bf16 stage images: [stage][o*72 + kk] (72-wide rows, 9216 bf16/stage)
static __device__ __align__(16) __nv_bfloat16 g_k2Ahi[36 * 9216], g_k2Alo[36 * 9216];
static __device__ __align__(16) __nv_bfloat16 g_k4Ahi[32 * 9216], g_k4Alo[32 * 9216];

// -------- K0: weight prep --------
__global__ void k0_prep(const float* __restrict__ w_dcn, const float* __restrict__ w_off,
                        const float* __restrict__ w_ct) {
    const int N_OFF = CINX * 27 * 9, N_K2 = 128 * 256 * 9, N_K4 = 262144;
    const int ntot = N_OFF + N_K2 + N_K4;
    for (int idx = blockIdx.x * blockDim.x + threadIdx.x; idx < ntot; idx += gridDim.x * blockDim.x) {
        if (idx < N_OFF) {
            const int c = idx / 243, r = idx - c * 243, o = r / 9, j = r - o * 9;
            g_wOffT[idx] = w_off[(o * CINX + c) * 9 + j];
        } else if (idx < N_OFF + N_K2) {
            const int r = idx - N_OFF, o = r & 127, c = (r >> 7) & 255, k = r >> 15;
            const float w = w_dcn[(o * CINX + c) * 9 + k];
            const int st = r >> 13, kk = (r >> 7) & 63;
            const __nv_bfloat16 hi = __float2bfloat16(w);
            g_k2Ahi[st * 9216 + o * 72 + kk] = hi;
            g_k2Alo[st * 9216 + o * 72 + kk] = __float2bfloat16(w - __bfloat162float(hi));
        } else {
            const int r2 = idx - N_OFF - N_K2;
            const int o = r2 & 127, c = (r2 >> 7) & 127, j = (r2 >> 14) & 7, P = r2 >> 17;
            const int wdh = P + 2 * (j >> 2), wdw = j & 3;
            const float w = w_ct[(c * NCO + o) * 16 + (3 - wdh) * 4 + (3 - wdw)];
            const int st = j * 2 + (c >> 6), kk = c & 63;
            const __nv_bfloat16 hi = __float2bfloat16(w);
            g_k4Ahi[(P * 16 + st) * 9216 + o * 72 + kk] = hi;
            g_k4Alo[(P * 16 + st) * 9216 + o * 72 + kk] = __float2bfloat16(w - __bfloat162float(hi));
        }
    }
}

// -------- K1: offset conv (FFMA) --------
__global__ __launch_bounds__(256, 2) void k1_offconv(const float* __restrict__ x,
                                                     const float* __restrict__ b_off) {
    const int b = blockIdx.x >> 6, h = blockIdx.x & 63, t = threadIdx.x;
    const int p = t & 63, g = t >> 6;
    __shared__ float sRow[3][68];
    __shared__ float sW[243];
    float acc[7];
#pragma unroll
    for (int i = 0; i < 7; i++) acc[i] = 0.f;
    const float* xb = x + (size_t)b * CINX * HWX;
    const int rr = t / 66, xx = t - rr * 66, gy = h - 1 + rr, gx = xx - 1;
    const bool xok = (t < 198) && (gy >= 0) && (gy < HH) && (gx >= 0) && (gx < WWD);
    const int xoff = gy * WWD + gx;
    float px_ = xok ? xb[xoff] : 0.f;
    float pw = (t < 243) ? g_wOffT[t] : 0.f;
    for (int c = 0; c < CINX; ++c) {
        __syncthreads();
        if (t < 198) sRow[rr][xx] = px_;
        if (t < 243) sW[t] = pw;
        __syncthreads();
        if (c + 1 < CINX) {
            px_ = xok ? xb[(size_t)(c + 1) * HWX + xoff] : 0.f;
            pw = (t < 243) ? g_wOffT[(c + 1) * 243 + t] : 0.f;
        }
        float xv[9];
#pragma unroll
        for (int r = 0; r < 3; r++)
#pragma unroll
            for (int cc = 0; cc < 3; cc++) xv[r * 3 + cc] = sRow[r][p + cc];
#pragma unroll
        for (int i = 0; i < 7; i++) {
            const int o = g + 4 * i;
            if (o < 27)
#pragma unroll
                for (int j = 0; j < 9; j++) acc[i] = fmaf(sW[o * 9 + j], xv[j], acc[i]);
        }
    }
#pragma unroll
    for (int i = 0; i < 7; i++) {
        const int o = g + 4 * i;
        if (o < 27) g_om[(((size_t)b * 27 + o) * 64 + h) * 64 + p] = acc[i] + b_off[o];
    }
}

// -------- K2: DCN sampling + mma.sync GEMM --------
// smem: Ahi[128*72] @0 (18432B), Alo @18432, Bhi[64*72] @36864 (9216B), Blo @46080,
//       sIdx @55296 (9216B), sWgt @64512 (9216B). total 73728.
#define K2_SMEM 73728
__global__ __launch_bounds__(256, 2) void k2_dcn_mma(const float* __restrict__ x,
                                                     const float* __restrict__ b_dcn) {
    extern __shared__ char sm[];
    const uint32_t sb = smem_u32(sm);
    const int b = blockIdx.x >> 6, h = blockIdx.x & 63, t = threadIdx.x;
    int* sIdx = (int*)(sm + 55296);
    float* sWgt = (float*)(sm + 64512);

    for (int item = t; item < 576; item += 256) {
        const int k = item >> 6, p = item & 63;
        const float oy = g_om[((b * 27 + k) * 64 + h) * 64 + p];
        const float ox = g_om[((b * 27 + 9 + k) * 64 + h) * 64 + p];
        const float mm = g_om[((b * 27 + 18 + k) * 64 + h) * 64 + p];
        const float mask = 1.0f / (1.0f + expf(-mm));
        const float py = oy + (float)(h - 1 + k / 3);
        const float pxx = ox + (float)(p - 1 + k % 3);
        const float y0f = floorf(py), x0f = floorf(pxx);
        const int y0 = (int)y0f, x0 = (int)x0f;
        const float ly = py - y0f, lx = pxx - x0f;
#pragma unroll
        for (int q = 0; q < 4; q++) {
            const int yi = y0 + (q >> 1), xi = x0 + (q & 1);
            const bool valid = (yi >= 0) && (yi < HH) && (xi >= 0) && (xi < WWD);
            sIdx[q * 576 + item] = min(max(yi, 0), HH - 1) * WWD + min(max(xi, 0), WWD - 1);
            const float wq = ((q >> 1) ? ly : 1.f - ly) * ((q & 1) ? lx : 1.f - lx);
            sWgt[q * 576 + item] = valid ? wq * mask : 0.f;
        }
    }
    __syncthreads();

    const float* xb = x + (size_t)b * CINX * HWX;
    const int p = t & 63, kkg = (t >> 6) * 16;
    const int w = t >> 5, L = t & 31;
    const int m0 = (w & 3) * 32, n0 = (w >> 2) * 32;
    // ldmatrix lane base addresses (k-offset added in loop)
    const uint32_t aA = sb + (m0 + (L & 15)) * 144 + ((L & 16) ? 16 : 0);
    const uint32_t aB = sb + 36864 + (n0 + (L & 7) + ((L & 16) ? 8 : 0)) * 144 + ((L & 8) ? 16 : 0);

    float acc[2][4][4];
#pragma unroll
    for (int i = 0; i < 2; i++)
#pragma unroll
        for (int j = 0; j < 4; j++)
#pragma unroll
            for (int q = 0; q < 4; q++) acc[i][j][q] = 0.f;

    for (int s = 0; s < 36; ++s) {
        __syncthreads();
        {  // stage A (flat copy of padded pre-split stage image)
            const uint4* gh = ((const uint4*)g_k2Ahi) + s * 1152;
            const uint4* gl = ((const uint4*)g_k2Alo) + s * 1152;
            uint4* dh = (uint4*)sm;
            uint4* dl = (uint4*)(sm + 18432);
            for (int i = t; i < 1152; i += 256) { dh[i] = gh[i]; dl[i] = gl[i]; }
        }
        // produce B: tap k, channels c0..c0+63
        const int k = s >> 2, c0 = (s & 3) * 64;
        const int i0 = sIdx[k * 64 + p], i1 = sIdx[576 + k * 64 + p];
        const int i2 = sIdx[1152 + k * 64 + p], i3 = sIdx[1728 + k * 64 + p];
        const float w0 = sWgt[k * 64 + p], w1 = sWgt[576 + k * 64 + p];
        const float w2 = sWgt[1152 + k * 64 + p], w3 = sWgt[1728 + k * 64 + p];
        char* Brow = sm + 36864 + p * 144;
#pragma unroll
        for (int i = 0; i < 16; i += 2) {
            const int kk = kkg + i;
            const float* xc0 = xb + (size_t)(c0 + kk) * HWX;
            const float* xc1 = xc0 + HWX;
            const float v0 = w0 * xc0[i0] + w1 * xc0[i1] + w2 * xc0[i2] + w3 * xc0[i3];
            const float v1 = w0 * xc1[i0] + w1 * xc1[i1] + w2 * xc1[i2] + w3 * xc1[i3];
            uint32_t ul, uh = packsplit(v0, v1, ul);
            *(uint32_t*)(Brow + kk * 2) = uh;
            *(uint32_t*)(Brow + 9216 + kk * 2) = ul;
        }
        __syncthreads();
#pragma unroll
        for (int ks = 0; ks < 4; ks++) {
            const uint32_t kb = ks * 32;
            uint32_t ah[2][4], al[2][4], bh[2][4], bl[2][4];
            ldsm4(aA + kb, ah[0]);
            ldsm4(aA + 2304 + kb, ah[1]);  // +16 rows *144
            ldsm4(aA + 18432 + kb, al[0]);
            ldsm4(aA + 18432 + 2304 + kb, al[1]);
            ldsm4(aB + kb, bh[0]);
            ldsm4(aB + 2304 + kb, bh[1]);  // ntiles 2,3
            ldsm4(aB + 9216 + kb, bl[0]);
            ldsm4(aB + 9216 + 2304 + kb, bl[1]);
#pragma unroll
            for (int tm = 0; tm < 2; tm++)
#pragma unroll
                for (int tn = 0; tn < 4; tn++) {
                    const uint32_t* BH = &bh[tn >> 1][(tn & 1) * 2];
                    const uint32_t* BL = &bl[tn >> 1][(tn & 1) * 2];
                    mma16816(acc[tm][tn], ah[tm], BH[0], BH[1]);
                    mma16816(acc[tm][tn], ah[tm], BL[0], BL[1]);
                    mma16816(acc[tm][tn], al[tm], BH[0], BH[1]);
                }
        }
    }
    // epilogue
#pragma unroll
    for (int tm = 0; tm < 2; tm++) {
        const int o = m0 + tm * 16 + (L >> 2);
        const float bv0 = b_dcn[o], bv1 = b_dcn[o + 8];
#pragma unroll
        for (int tn = 0; tn < 4; tn++) {
            const int pc = n0 + tn * 8 + (L & 3) * 2;
            float* base = g_out1 + (((size_t)b * NCO + o) * 64 + h) * 64 + pc;
            float2 v0 = {acc[tm][tn][0] + bv0, acc[tm][tn][1] + bv0};
            float2 v1 = {acc[tm][tn][2] + bv1, acc[tm][tn][3] + bv1};
            *(float2*)base = v0;
            *(float2*)(base + 8 * HWX) = v1;
        }
    }
}

// -------- K3/K5: BN stats --------
__device__ __forceinline__ void bn_stats(const float* base, int nper, const float* gamma,
                                         const float* beta, float* out) {
    const int ch = blockIdx.x, t = threadIdx.x;
    float s = 0.f, q = 0.f;
    for (int b = 0; b < NB; b++) {
        const float4* pch = (const float4*)(base + ((size_t)b * NCO + ch) * nper);
        for (int i = t; i < nper / 4; i += 256) {
            const float4 v = pch[i];
            s += v.x + v.y + v.z + v.w;
            q += v.x * v.x + v.y * v.y + v.z * v.z + v.w * v.w;
        }
    }
    __shared__ float rs[256], rq[256];
    rs[t] = s; rq[t] = q;
    __syncthreads();
    for (int off = 128; off > 0; off >>= 1) {
        if (t < off) { rs[t] += rs[t + off]; rq[t] += rq[t + off]; }
        __syncthreads();
    }
    if (t == 0) {
        const float n = (float)(NB * nper);
        const float mean = rs[0] / n;
        const float var = rq[0] / n - mean * mean;
        const float sc = rsqrtf(var + EPSV) * gamma[ch];
        out[ch] = sc;
        out[NCO + ch] = beta[ch] - mean * sc;
    }
}
__global__ void k3_stats1(const float* __restrict__ g, const float* __restrict__ b) {
    bn_stats(g_out1, HWX, g, b, g_stats1);
}
__global__ void k5_stats2(const float* __restrict__ o2, const float* __restrict__ g,
                          const float* __restrict__ b) {
    bn_stats(o2, 16384, g, b, g_stats2);
}

// -------- K4: transposed conv via mma.sync --------
// smem: Ahi @0, Alo @18432, Bhi @36864, Blo @46080. total 55296.
#define K4_SMEM 55296
__global__ __launch_bounds__(256, 2) void k4_tconv_mma(float* __restrict__ out2) {
    extern __shared__ char sm[];
    const uint32_t sb = smem_u32(sm);
    const int blk = blockIdx.x, b = blk >> 8, Y = (blk >> 1) & 127, X0 = (blk & 1) * 64;
    const int t = threadIdx.x, Ypar = Y & 1, y0r = (Y - 2 + Ypar) / 2;
    const int rX = t & 63, kkg = (t >> 6) * 16, Xg = X0 + rX;
    const int w = t >> 5, L = t & 31;
    const int m0 = (w & 3) * 32, n0 = (w >> 2) * 32;
    const uint32_t aA = sb + (m0 + (L & 15)) * 144 + ((L & 16) ? 16 : 0);
    const uint32_t aB = sb + 36864 + (n0 + (L & 7) + ((L & 16) ? 8 : 0)) * 144 + ((L & 8) ? 16 : 0);

    float acc[2][4][4];
#pragma unroll
    for (int i = 0; i < 2; i++)
#pragma unroll
        for (int j = 0; j < 4; j++)
#pragma unroll
            for (int q = 0; q < 4; q++) acc[i][j][q] = 0.f;

    for (int s = 0; s < 16; ++s) {
        __syncthreads();
        {
            const uint4* gh = ((const uint4*)g_k4Ahi) + (Ypar * 16 + s) * 1152;
            const uint4* gl = ((const uint4*)g_k4Alo) + (Ypar * 16 + s) * 1152;
            uint4* dh = (uint4*)sm;
            uint4* dl = (uint4*)(sm + 18432);
            for (int i = t; i < 1152; i += 256) { dh[i] = gh[i]; dl[i] = gl[i]; }
        }
        const int j = s >> 1, c0 = (s & 1) * 64, r = j >> 2, dw = j & 3;
        const int yrow = y0r + r;
        const int col = ((Xg + (Xg & 1)) >> 1) + (dw >> 1);
        const int gx = col - 1;
        const bool ok = (((Xg ^ dw) & 1) == 0) && (yrow >= 0) && (yrow < HH) && (gx >= 0) && (gx < WWD);
        char* Brow = sm + 36864 + rX * 144;
#pragma unroll
        for (int i = 0; i < 16; i += 2) {
            const int kk = kkg + i;
            float v0 = 0.f, v1 = 0.f;
            if (ok) {
                const size_t base = (((size_t)b * NCO + c0 + kk) * 64 + yrow) * 64 + gx;
                v0 = fmaxf(0.f, fmaf(g_out1[base], g_stats1[c0 + kk], g_stats1[NCO + c0 + kk]));
                v1 = fmaxf(0.f, fmaf(g_out1[base + HWX], g_stats1[c0 + kk + 1], g_stats1[NCO + c0 + kk + 1]));
            }
            uint32_t ul, uh = packsplit(v0, v1, ul);
            *(uint32_t*)(Brow + kk * 2) = uh;
            *(uint32_t*)(Brow + 9216 + kk * 2) = ul;
        }
        __syncthreads();
#pragma unroll
        for (int ks = 0; ks < 4; ks++) {
            const uint32_t kb = ks * 32;
            uint32_t ah[2][4], al[2][4], bh[2][4], bl[2][4];
            ldsm4(aA + kb, ah[0]);
            ldsm4(aA + 2304 + kb, ah[1]);
            ldsm4(aA + 18432 + kb, al[0]);
            ldsm4(aA + 18432 + 2304 + kb, al[1]);
            ldsm4(aB + kb, bh[0]);
            ldsm4(aB + 2304 + kb, bh[1]);
            ldsm4(aB + 9216 + kb, bl[0]);
            ldsm4(aB + 9216 + 2304 + kb, bl[1]);
#pragma unroll
            for (int tm = 0; tm < 2; tm++)
#pragma unroll
                for (int tn = 0; tn < 4; tn++) {
                    const uint32_t* BH = &bh[tn >> 1][(tn & 1) * 2];
                    const uint32_t* BL = &bl[tn >> 1][(tn & 1) * 2];
                    mma16816(acc[tm][tn], ah[tm], BH[0], BH[1]);
                    mma16816(acc[tm][tn], ah[tm], BL[0], BL[1]);
                    mma16816(acc[tm][tn], al[tm], BH[0], BH[1]);
                }
        }
    }
#pragma unroll
    for (int tm = 0; tm < 2; tm++) {
        const int o = m0 + tm * 16 + (L >> 2);
#pragma unroll
        for (int tn = 0; tn < 4; tn++) {
            const int X = X0 + n0 + tn * 8 + (L & 3) * 2;
            float* base = out2 + (((size_t)b * NCO + o) * 128 + Y) * 128 + X;
            float2 v0 = {acc[tm][tn][0], acc[tm][tn][1]};
            float2 v1 = {acc[tm][tn][2], acc[tm][tn][3]};
            *(float2*)base = v0;
            *(float2*)(base + 8 * 16384) = v1;
        }
    }
}

// -------- K6: in-place BN2+ReLU --------
__global__ void k6_bnrelu(float* __restrict__ out) {
    const int n4 = NB * NCO * 128 * 128 / 4;
    int i4 = blockIdx.x * blockDim.x + threadIdx.x;
    if (i4 < n4) {
        float4 v = ((float4*)out)[i4];
        const int ch = (i4 >> 12) & 127;
        const float sc = g_stats2[ch], sh = g_stats2[NCO + ch];
        v.x = fmaxf(0.f, fmaf(v.x, sc, sh));
        v.y = fmaxf(0.f, fmaf(v.y, sc, sh));
        v.z = fmaxf(0.f, fmaf(v.z, sc, sh));
        v.w = fmaxf(0.f, fmaf(v.w, sc, sh));
        ((float4*)out)[i4] = v;
    }
}

extern "C" void kernel_launch(void* const* d_in, const int* in_sizes, int n_in,
                              void* d_out, int out_size) {
    const float* x = (const float*)d_in[0];
    const float* w_off = (const float*)d_in[1];
    const float* b_off = (const float*)d_in[2];
    const float* w_dcn = (const float*)d_in[3];
    const float* b_dcn = (const float*)d_in[4];
    const float* gamma1 = (const float*)d_in[5];
    const float* beta1 = (const float*)d_in[6];
    const float* w_ct = (const float*)d_in[7];
    const float* gamma2 = (const float*)d_in[8];
    const float* beta2 = (const float*)d_in[9];
    float* out = (float*)d_out;
    (void)in_sizes; (void)n_in; (void)out_size;

    static int attr_done = 0;
    if (!attr_done) {
        cudaFuncSetAttribute(k2_dcn_mma, cudaFuncAttributeMaxDynamicSharedMemorySize, K2_SMEM);
        cudaFuncSetAttribute(k4_tconv_mma, cudaFuncAttributeMaxDynamicSharedMemorySize, K4_SMEM);
        attr_done = 1;
    }
    k0_prep<<<256, 256>>>(w_dcn, w_off, w_ct);
    k1_offconv<<<NB * HH, 256>>>(x, b_off);
    k2_dcn_mma<<<NB * HH, 256, K2_SMEM>>>(x, b_dcn);
    k3_stats1<<<NCO, 256>>>(gamma1, beta1);
    k4_tconv_mma<<<NB * 128 * 2, 256, K4_SMEM>>>(out);
    k5_stats2<<<NCO, 256>>>(out, gamma2, beta2);
    k6_bnrelu<<<(NB * NCO * 128 * 128 / 4 + 255) / 256, 256>>>(out);
}

// round 5
// speedup vs baseline: 2.7717x; 1.3303x over previous
#include <cuda_runtime.h>
#include <cuda_bf16.h>
#include <math.h>
#include <stdint.h>

#define NB 8
#define CINX 256
#define NCO 128
#define HH 64
#define WWD 64
#define HWX 4096
#define EPSV 1e-5f

__device__ __forceinline__ uint32_t smem_u32(const void* p) {
    uint32_t a;
    asm("{ .reg .u64 t; cvta.to.shared.u64 t, %1; cvt.u32.u64 %0, t; }" : "=r"(a) : "l"(p));
    return a;
}
__device__ __forceinline__ void ldsm4(uint32_t addr, uint32_t r[4]) {
    asm volatile("ldmatrix.sync.aligned.m8n8.x4.shared.b16 {%0,%1,%2,%3},[%4];"
                 : "=r"(r[0]), "=r"(r[1]), "=r"(r[2]), "=r"(r[3]) : "r"(addr));
}
__device__ __forceinline__ void mma16816(float d[4], const uint32_t a[4], const uint32_t b0,
                                         const uint32_t b1) {
    asm volatile("mma.sync.aligned.m16n8k16.row.col.f32.bf16.bf16.f32 "
                 "{%0,%1,%2,%3},{%4,%5,%6,%7},{%8,%9},{%0,%1,%2,%3};"
                 : "+f"(d[0]), "+f"(d[1]), "+f"(d[2]), "+f"(d[3])
                 : "r"(a[0]), "r"(a[1]), "r"(a[2]), "r"(a[3]), "r"(b0), "r"(b1));
}
__device__ __forceinline__ uint32_t packsplit(float v0, float v1, uint32_t& lo) {
    __nv_bfloat16 h0 = __float2bfloat16(v0), h1 = __float2bfloat16(v1);
    __nv_bfloat16 l0 = __float2bfloat16(v0 - __bfloat162float(h0));
    __nv_bfloat16 l1 = __float2bfloat16(v1 - __bfloat162float(h1));
    lo = (uint32_t)__bfloat16_as_ushort(l0) | ((uint32_t)__bfloat16_as_ushort(l1) << 16);
    return (uint32_t)__bfloat16_as_ushort(h0) | ((uint32_t)__bfloat16_as_ushort(h1) << 16);
}

// -------- scratch --------
static __device__ float g_om[NB * 27 * HWX];
static __device__ float g_out1[NB * NCO * HWX];
static __device__ float g_stats1[2 * NCO];
static __device__ float g_stats2[2 * NCO];
static __device__ float g_p1[NB * NCO * 2];
static __device__ float g_p2[NB * NCO * 2];
// padded bf16 stage images (72-wide rows)
static __device__ __align__(16) __nv_bfloat16 g_k1Ahi[36 * 2304], g_k1Alo[36 * 2304];
static __device__ __align__(16) __nv_bfloat16 g_k2Ahi[36 * 9216], g_k2Alo[36 * 9216];
static __device__ __align__(16) __nv_bfloat16 g_k4Ahi[32 * 9216], g_k4Alo[32 * 9216];

// -------- K0: weight prep --------
__global__ void k0_prep(const float* __restrict__ w_dcn, const float* __restrict__ w_off,
                        const float* __restrict__ w_ct) {
    const int N_K1 = 36 * 2048, N_K2 = 128 * 256 * 9, N_K4 = 262144;
    const int ntot = N_K1 + N_K2 + N_K4;
    for (int idx = blockIdx.x * blockDim.x + threadIdx.x; idx < ntot; idx += gridDim.x * blockDim.x) {
        if (idx < N_K1) {
            const int st = idx >> 11, o = (idx >> 6) & 31, kk = idx & 63;
            const int c = (st & 3) * 64 + kk, j = st >> 2;
            const float w = (o < 27) ? w_off[(o * CINX + c) * 9 + j] : 0.f;
            const __nv_bfloat16 hi = __float2bfloat16(w);
            g_k1Ahi[st * 2304 + o * 72 + kk] = hi;
            g_k1Alo[st * 2304 + o * 72 + kk] = __float2bfloat16(w - __bfloat162float(hi));
        } else if (idx < N_K1 + N_K2) {
            const int r = idx - N_K1, o = r & 127, c = (r >> 7) & 255, k = r >> 15;
            const float w = w_dcn[(o * CINX + c) * 9 + k];
            const int st = r >> 13, kk = (r >> 7) & 63;
            const __nv_bfloat16 hi = __float2bfloat16(w);
            g_k2Ahi[st * 9216 + o * 72 + kk] = hi;
            g_k2Alo[st * 9216 + o * 72 + kk] = __float2bfloat16(w - __bfloat162float(hi));
        } else {
            const int r2 = idx - N_K1 - N_K2;
            const int o = r2 & 127, c = (r2 >> 7) & 127, j = (r2 >> 14) & 7, P = r2 >> 17;
            const int wdh = P + 2 * (j >> 2), wdw = j & 3;
            const float w = w_ct[(c * NCO + o) * 16 + (3 - wdh) * 4 + (3 - wdw)];
            const int st = j * 2 + (c >> 6), kk = c & 63;
            const __nv_bfloat16 hi = __float2bfloat16(w);
            g_k4Ahi[(P * 16 + st) * 9216 + o * 72 + kk] = hi;
            g_k4Alo[(P * 16 + st) * 9216 + o * 72 + kk] = __float2bfloat16(w - __bfloat162float(hi));
        }
    }
}

// -------- K1: offset conv via mma.sync --------
// smem: Ahi[32*72] @0 (4608B), Alo @4608, Bhi[64*72] @9216, Blo @18432. total 27648.
__global__ __launch_bounds__(256) void k1_off_mma(const float* __restrict__ x,
                                                  const float* __restrict__ b_off) {
    __shared__ __align__(16) char sm[27648];
    const uint32_t sb = smem_u32(sm);
    const int b = blockIdx.x >> 6, h = blockIdx.x & 63, t = threadIdx.x;
    const int p = t & 63, kkg = (t >> 6) * 16;
    const int w = t >> 5, L = t & 31;
    const int m0 = (w & 1) * 16, n0 = (w >> 1) * 16;
    const uint32_t aA = sb + (m0 + (L & 15)) * 144 + ((L & 16) ? 16 : 0);
    const uint32_t aB = sb + 9216 + (n0 + (L & 7) + ((L & 16) ? 8 : 0)) * 144 + ((L & 8) ? 16 : 0);
    const float* xb = x + (size_t)b * CINX * HWX;

    float acc[2][4];
#pragma unroll
    for (int i = 0; i < 2; i++)
#pragma unroll
        for (int q = 0; q < 4; q++) acc[i][q] = 0.f;

    for (int s = 0; s < 36; ++s) {
        __syncthreads();
        {  // stage A: 2 x 4608 B = 2 x 288 uint4
            const uint4* gh = ((const uint4*)g_k1Ahi) + s * 288;
            const uint4* gl = ((const uint4*)g_k1Alo) + s * 288;
            uint4* dh = (uint4*)sm;
            uint4* dl = (uint4*)(sm + 4608);
            dh[t % 288] = gh[t % 288];  // covers 0..255
            if (t < 32) { dh[256 + t] = gh[256 + t]; }
            dl[t % 288] = gl[t % 288];
            if (t < 32) { dl[256 + t] = gl[256 + t]; }
        }
        const int j = s >> 2, c0 = (s & 3) * 64;
        const int jy = j / 3, jx = j - jy * 3;
        const int row = h - 1 + jy, col = p - 1 + jx;
        const bool ok = (row >= 0) && (row < HH) && (col >= 0) && (col < WWD);
        const float* xcol = xb + row * WWD + col;
        char* Brow = sm + 9216 + p * 144;
#pragma unroll
        for (int i = 0; i < 16; i += 2) {
            const int kk = kkg + i;
            float v0 = 0.f, v1 = 0.f;
            if (ok) {
                v0 = xcol[(size_t)(c0 + kk) * HWX];
                v1 = xcol[(size_t)(c0 + kk + 1) * HWX];
            }
            uint32_t ul, uh = packsplit(v0, v1, ul);
            *(uint32_t*)(Brow + kk * 2) = uh;
            *(uint32_t*)(Brow + 9216 + kk * 2) = ul;
        }
        __syncthreads();
#pragma unroll
        for (int ks = 0; ks < 4; ks++) {
            const uint32_t kb = ks * 32;
            uint32_t ah[4], al[4], bh[4], bl[4];
            ldsm4(aA + kb, ah);
            ldsm4(aA + 4608 + kb, al);
            ldsm4(aB + kb, bh);
            ldsm4(aB + 9216 + kb, bl);
#pragma unroll
            for (int tn = 0; tn < 2; tn++) {
                mma16816(acc[tn], ah, bh[tn * 2], bh[tn * 2 + 1]);
                mma16816(acc[tn], ah, bl[tn * 2], bl[tn * 2 + 1]);
                mma16816(acc[tn], al, bh[tn * 2], bh[tn * 2 + 1]);
            }
        }
    }
    const int o = m0 + (L >> 2);
#pragma unroll
    for (int tn = 0; tn < 2; tn++) {
        const int pc = n0 + tn * 8 + (L & 3) * 2;
        if (o < 27) {
            const float bv = b_off[o];
            float2 v = {acc[tn][0] + bv, acc[tn][1] + bv};
            *(float2*)(g_om + (((size_t)b * 27 + o) * 64 + h) * 64 + pc) = v;
        }
        if (o + 8 < 27) {
            const float bv = b_off[o + 8];
            float2 v = {acc[tn][2] + bv, acc[tn][3] + bv};
            *(float2*)(g_om + (((size_t)b * 27 + o + 8) * 64 + h) * 64 + pc) = v;
        }
    }
}

// -------- K2: DCN sampling + mma.sync GEMM --------
#define K2_SMEM 73728
__global__ __launch_bounds__(256, 2) void k2_dcn_mma(const float* __restrict__ x,
                                                     const float* __restrict__ b_dcn) {
    extern __shared__ char sm[];
    const uint32_t sb = smem_u32(sm);
    const int b = blockIdx.x >> 6, h = blockIdx.x & 63, t = threadIdx.x;
    int* sIdx = (int*)(sm + 55296);
    float* sWgt = (float*)(sm + 64512);

    for (int item = t; item < 576; item += 256) {
        const int k = item >> 6, p = item & 63;
        const float oy = g_om[((b * 27 + k) * 64 + h) * 64 + p];
        const float ox = g_om[((b * 27 + 9 + k) * 64 + h) * 64 + p];
        const float mm = g_om[((b * 27 + 18 + k) * 64 + h) * 64 + p];
        const float mask = 1.0f / (1.0f + expf(-mm));
        const float py = oy + (float)(h - 1 + k / 3);
        const float pxx = ox + (float)(p - 1 + k % 3);
        const float y0f = floorf(py), x0f = floorf(pxx);
        const int y0 = (int)y0f, x0 = (int)x0f;
        const float ly = py - y0f, lx = pxx - x0f;
#pragma unroll
        for (int q = 0; q < 4; q++) {
            const int yi = y0 + (q >> 1), xi = x0 + (q & 1);
            const bool valid = (yi >= 0) && (yi < HH) && (xi >= 0) && (xi < WWD);
            sIdx[q * 576 + item] = min(max(yi, 0), HH - 1) * WWD + min(max(xi, 0), WWD - 1);
            const float wq = ((q >> 1) ? ly : 1.f - ly) * ((q & 1) ? lx : 1.f - lx);
            sWgt[q * 576 + item] = valid ? wq * mask : 0.f;
        }
    }
    __syncthreads();

    const float* xb = x + (size_t)b * CINX * HWX;
    const int p = t & 63, kkg = (t >> 6) * 16;
    const int w = t >> 5, L = t & 31;
    const int m0 = (w & 3) * 32, n0 = (w >> 2) * 32;
    const uint32_t aA = sb + (m0 + (L & 15)) * 144 + ((L & 16) ? 16 : 0);
    const uint32_t aB = sb + 36864 + (n0 + (L & 7) + ((L & 16) ? 8 : 0)) * 144 + ((L & 8) ? 16 : 0);

    float acc[2][4][4];
#pragma unroll
    for (int i = 0; i < 2; i++)
#pragma unroll
        for (int j = 0; j < 4; j++)
#pragma unroll
            for (int q = 0; q < 4; q++) acc[i][j][q] = 0.f;

    for (int s = 0; s < 36; ++s) {
        __syncthreads();
        {
            const uint4* gh = ((const uint4*)g_k2Ahi) + s * 1152;
            const uint4* gl = ((const uint4*)g_k2Alo) + s * 1152;
            uint4* dh = (uint4*)sm;
            uint4* dl = (uint4*)(sm + 18432);
            for (int i = t; i < 1152; i += 256) { dh[i] = gh[i]; dl[i] = gl[i]; }
        }
        const int k = s >> 2, c0 = (s & 3) * 64;
        const int i0 = sIdx[k * 64 + p], i1 = sIdx[576 + k * 64 + p];
        const int i2 = sIdx[1152 + k * 64 + p], i3 = sIdx[1728 + k * 64 + p];
        const float w0 = sWgt[k * 64 + p], w1 = sWgt[576 + k * 64 + p];
        const float w2 = sWgt[1152 + k * 64 + p], w3 = sWgt[1728 + k * 64 + p];
        char* Brow = sm + 36864 + p * 144;
#pragma unroll
        for (int i = 0; i < 16; i += 2) {
            const int kk = kkg + i;
            const float* xc0 = xb + (size_t)(c0 + kk) * HWX;
            const float* xc1 = xc0 + HWX;
            const float v0 = w0 * xc0[i0] + w1 * xc0[i1] + w2 * xc0[i2] + w3 * xc0[i3];
            const float v1 = w0 * xc1[i0] + w1 * xc1[i1] + w2 * xc1[i2] + w3 * xc1[i3];
            uint32_t ul, uh = packsplit(v0, v1, ul);
            *(uint32_t*)(Brow + kk * 2) = uh;
            *(uint32_t*)(Brow + 9216 + kk * 2) = ul;
        }
        __syncthreads();
#pragma unroll
        for (int ks = 0; ks < 4; ks++) {
            const uint32_t kb = ks * 32;
            uint32_t ah[2][4], al[2][4], bh[2][4], bl[2][4];
            ldsm4(aA + kb, ah[0]);
            ldsm4(aA + 2304 + kb, ah[1]);
            ldsm4(aA + 18432 + kb, al[0]);
            ldsm4(aA + 18432 + 2304 + kb, al[1]);
            ldsm4(aB + kb, bh[0]);
            ldsm4(aB + 2304 + kb, bh[1]);
            ldsm4(aB + 9216 + kb, bl[0]);
            ldsm4(aB + 9216 + 2304 + kb, bl[1]);
#pragma unroll
            for (int tm = 0; tm < 2; tm++)
#pragma unroll
                for (int tn = 0; tn < 4; tn++) {
                    const uint32_t* BH = &bh[tn >> 1][(tn & 1) * 2];
                    const uint32_t* BL = &bl[tn >> 1][(tn & 1) * 2];
                    mma16816(acc[tm][tn], ah[tm], BH[0], BH[1]);
                    mma16816(acc[tm][tn], ah[tm], BL[0], BL[1]);
                    mma16816(acc[tm][tn], al[tm], BH[0], BH[1]);
                }
        }
    }
#pragma unroll
    for (int tm = 0; tm < 2; tm++) {
        const int o = m0 + tm * 16 + (L >> 2);
        const float bv0 = b_dcn[o], bv1 = b_dcn[o + 8];
#pragma unroll
        for (int tn = 0; tn < 4; tn++) {
            const int pc = n0 + tn * 8 + (L & 3) * 2;
            float* base = g_out1 + (((size_t)b * NCO + o) * 64 + h) * 64 + pc;
            float2 v0 = {acc[tm][tn][0] + bv0, acc[tm][tn][1] + bv0};
            float2 v1 = {acc[tm][tn][2] + bv1, acc[tm][tn][3] + bv1};
            *(float2*)base = v0;
            *(float2*)(base + 8 * HWX) = v1;
        }
    }
}

// -------- stats: per-(b,ch) plane partials + finalize (deterministic) --------
__device__ __forceinline__ void pstats_body(const float* __restrict__ plane, int n4,
                                            float* __restrict__ part) {
    const int t = threadIdx.x;
    const float4* pch = (const float4*)plane;
    float s = 0.f, q = 0.f;
    for (int i = t; i < n4; i += 256) {
        const float4 v = pch[i];
        s += v.x + v.y + v.z + v.w;
        q += v.x * v.x + v.y * v.y + v.z * v.z + v.w * v.w;
    }
    __shared__ float rs[256], rq[256];
    rs[t] = s; rq[t] = q;
    __syncthreads();
    for (int off = 128; off > 0; off >>= 1) {
        if (t < off) { rs[t] += rs[t + off]; rq[t] += rq[t + off]; }
        __syncthreads();
    }
    if (t == 0) { part[blockIdx.x * 2] = rs[0]; part[blockIdx.x * 2 + 1] = rq[0]; }
}
__global__ void k3a_pstats() {
    pstats_body(g_out1 + (size_t)blockIdx.x * HWX, HWX / 4, g_p1);
}
__global__ void k5a_pstats(const float* __restrict__ o2) {
    pstats_body(o2 + (size_t)blockIdx.x * 16384, 16384 / 4, g_p2);
}
__device__ __forceinline__ void finalize_body(const float* part, float nelem,
                                              const float* gamma, const float* beta,
                                              float* stats) {
    const int ch = threadIdx.x;
    float s = 0.f, q = 0.f;
    for (int b = 0; b < NB; b++) {
        s += part[(b * NCO + ch) * 2];
        q += part[(b * NCO + ch) * 2 + 1];
    }
    const float mean = s / nelem;
    const float var = q / nelem - mean * mean;
    const float sc = rsqrtf(var + EPSV) * gamma[ch];
    stats[ch] = sc;
    stats[NCO + ch] = beta[ch] - mean * sc;
}
__global__ void k3b_fin(const float* __restrict__ g, const float* __restrict__ b) {
    finalize_body(g_p1, (float)(NB * HWX), g, b, g_stats1);
}
__global__ void k5b_fin(const float* __restrict__ g, const float* __restrict__ b) {
    finalize_body(g_p2, (float)(NB * 16384), g, b, g_stats2);
}

// -------- K4: transposed conv via mma.sync --------
#define K4_SMEM 55296
__global__ __launch_bounds__(256, 2) void k4_tconv_mma(float* __restrict__ out2) {
    extern __shared__ char sm[];
    const uint32_t sb = smem_u32(sm);
    const int blk = blockIdx.x, b = blk >> 8, Y = (blk >> 1) & 127, X0 = (blk & 1) * 64;
    const int t = threadIdx.x, Ypar = Y & 1, y0r = (Y - 2 + Ypar) / 2;
    const int rX = t & 63, kkg = (t >> 6) * 16, Xg = X0 + rX;
    const int w = t >> 5, L = t & 31;
    const int m0 = (w & 3) * 32, n0 = (w >> 2) * 32;
    const uint32_t aA = sb + (m0 + (L & 15)) * 144 + ((L & 16) ? 16 : 0);
    const uint32_t aB = sb + 36864 + (n0 + (L & 7) + ((L & 16) ? 8 : 0)) * 144 + ((L & 8) ? 16 : 0);

    float acc[2][4][4];
#pragma unroll
    for (int i = 0; i < 2; i++)
#pragma unroll
        for (int j = 0; j < 4; j++)
#pragma unroll
            for (int q = 0; q < 4; q++) acc[i][j][q] = 0.f;

    for (int s = 0; s < 16; ++s) {
        __syncthreads();
        {
            const uint4* gh = ((const uint4*)g_k4Ahi) + (Ypar * 16 + s) * 1152;
            const uint4* gl = ((const uint4*)g_k4Alo) + (Ypar * 16 + s) * 1152;
            uint4* dh = (uint4*)sm;
            uint4* dl = (uint4*)(sm + 18432);
            for (int i = t; i < 1152; i += 256) { dh[i] = gh[i]; dl[i] = gl[i]; }
        }
        const int j = s >> 1, c0 = (s & 1) * 64, r = j >> 2, dw = j & 3;
        const int yrow = y0r + r;
        const int col = ((Xg + (Xg & 1)) >> 1) + (dw >> 1);
        const int gx = col - 1;
        const bool ok = (((Xg ^ dw) & 1) == 0) && (yrow >= 0) && (yrow < HH) && (gx >= 0) && (gx < WWD);
        char* Brow = sm + 36864 + rX * 144;
#pragma unroll
        for (int i = 0; i < 16; i += 2) {
            const int kk = kkg + i;
            float v0 = 0.f, v1 = 0.f;
            if (ok) {
                const size_t base = (((size_t)b * NCO + c0 + kk) * 64 + yrow) * 64 + gx;
                v0 = fmaxf(0.f, fmaf(g_out1[base], g_stats1[c0 + kk], g_stats1[NCO + c0 + kk]));
                v1 = fmaxf(0.f, fmaf(g_out1[base + HWX], g_stats1[c0 + kk + 1], g_stats1[NCO + c0 + kk + 1]));
            }
            uint32_t ul, uh = packsplit(v0, v1, ul);
            *(uint32_t*)(Brow + kk * 2) = uh;
            *(uint32_t*)(Brow + 9216 + kk * 2) = ul;
        }
        __syncthreads();
#pragma unroll
        for (int ks = 0; ks < 4; ks++) {
            const uint32_t kb = ks * 32;
            uint32_t ah[2][4], al[2][4], bh[2][4], bl[2][4];
            ldsm4(aA + kb, ah[0]);
            ldsm4(aA + 2304 + kb, ah[1]);
            ldsm4(aA + 18432 + kb, al[0]);
            ldsm4(aA + 18432 + 2304 + kb, al[1]);
            ldsm4(aB + kb, bh[0]);
            ldsm4(aB + 2304 + kb, bh[1]);
            ldsm4(aB + 9216 + kb, bl[0]);
            ldsm4(aB + 9216 + 2304 + kb, bl[1]);
#pragma unroll
            for (int tm = 0; tm < 2; tm++)
#pragma unroll
                for (int tn = 0; tn < 4; tn++) {
                    const uint32_t* BH = &bh[tn >> 1][(tn & 1) * 2];
                    const uint32_t* BL = &bl[tn >> 1][(tn & 1) * 2];
                    mma16816(acc[tm][tn], ah[tm], BH[0], BH[1]);
                    mma16816(acc[tm][tn], ah[tm], BL[0], BL[1]);
                    mma16816(acc[tm][tn], al[tm], BH[0], BH[1]);
                }
        }
    }
#pragma unroll
    for (int tm = 0; tm < 2; tm++) {
        const int o = m0 + tm * 16 + (L >> 2);
#pragma unroll
        for (int tn = 0; tn < 4; tn++) {
            const int X = X0 + n0 + tn * 8 + (L & 3) * 2;
            float* base = out2 + (((size_t)b * NCO + o) * 128 + Y) * 128 + X;
            float2 v0 = {acc[tm][tn][0], acc[tm][tn][1]};
            float2 v1 = {acc[tm][tn][2], acc[tm][tn][3]};
            *(float2*)base = v0;
            *(float2*)(base + 8 * 16384) = v1;
        }
    }
}

// -------- K6: in-place BN2+ReLU --------
__global__ void k6_bnrelu(float* __restrict__ out) {
    const int n4 = NB * NCO * 128 * 128 / 4;
    int i4 = blockIdx.x * blockDim.x + threadIdx.x;
    if (i4 < n4) {
        float4 v = ((float4*)out)[i4];
        const int ch = (i4 >> 12) & 127;
        const float sc = g_stats2[ch], sh = g_stats2[NCO + ch];
        v.x = fmaxf(0.f, fmaf(v.x, sc, sh));
        v.y = fmaxf(0.f, fmaf(v.y, sc, sh));
        v.z = fmaxf(0.f, fmaf(v.z, sc, sh));
        v.w = fmaxf(0.f, fmaf(v.w, sc, sh));
        ((float4*)out)[i4] = v;
    }
}

extern "C" void kernel_launch(void* const* d_in, const int* in_sizes, int n_in,
                              void* d_out, int out_size) {
    const float* x = (const float*)d_in[0];
    const float* w_off = (const float*)d_in[1];
    const float* b_off = (const float*)d_in[2];
    const float* w_dcn = (const float*)d_in[3];
    const float* b_dcn = (const float*)d_in[4];
    const float* gamma1 = (const float*)d_in[5];
    const float* beta1 = (const float*)d_in[6];
    const float* w_ct = (const float*)d_in[7];
    const float* gamma2 = (const float*)d_in[8];
    const float* beta2 = (const float*)d_in[9];
    float* out = (float*)d_out;
    (void)in_sizes; (void)n_in; (void)out_size;

    static int attr_done = 0;
    if (!attr_done) {
        cudaFuncSetAttribute(k2_dcn_mma, cudaFuncAttributeMaxDynamicSharedMemorySize, K2_SMEM);
        cudaFuncSetAttribute(k4_tconv_mma, cudaFuncAttributeMaxDynamicSharedMemorySize, K4_SMEM);
        attr_done = 1;
    }
    k0_prep<<<256, 256>>>(w_dcn, w_off, w_ct);
    k1_off_mma<<<NB * HH, 256>>>(x, b_off);
    k2_dcn_mma<<<NB * HH, 256, K2_SMEM>>>(x, b_dcn);
    k3a_pstats<<<NB * NCO, 256>>>();
    k3b_fin<<<1, NCO>>>(gamma1, beta1);
    k4_tconv_mma<<<NB * 128 * 2, 256, K4_SMEM>>>(out);
    k5a_pstats<<<NB * NCO, 256>>>(out);
    k5b_fin<<<1, NCO>>>(gamma2, beta2);
    k6_bnrelu<<<(NB * NCO * 128 * 128 / 4 + 255) / 256, 256>>>(out);
}